// round 15
// baseline (speedup 1.0000x reference)
#include <cuda_runtime.h>
#include <cstdint>

#define NB    2
#define NA    9
#define NHW   4096        // 64*64
#define NPROP 36864       // NHW*NA
#define NPAD  65536
#define TOPN  2000
#define WIN   1024        // candidates per window
#define WRD   16          // 64-bit words per window
#define NWIN  36          // WIN*NWIN = NPROP

typedef unsigned long long u64;

// Anchors from generate_anchors(16,(0.5,1,2),(8,16,32)) with base [0,0,15,15].
__constant__ float c_anchors[9][4] = {
  { -84.f,  -40.f,  99.f,  55.f},
  {-176.f,  -88.f, 191.f, 103.f},
  {-360.f, -184.f, 375.f, 199.f},
  { -56.f,  -56.f,  71.f,  71.f},
  {-120.f, -120.f, 135.f, 135.f},
  {-248.f, -248.f, 263.f, 263.f},
  { -36.f,  -80.f,  51.f,  95.f},
  { -80.f, -168.f,  95.f, 183.f},
  {-168.f, -344.f, 183.f, 359.f}
};

__device__ float4 g_boxes [NB][NPROP];
__device__ float  g_scores[NB][NPROP];
__device__ u64    g_keys  [NB * NPAD];
__device__ float4 g_sbox  [NB][NPROP];
__device__ float  g_sscore[NB][NPROP];
__device__ float  g_sarea [NB][NPROP];
__device__ u64    g_wmask [2][NB][WRD][WIN]; // double-buffered window masks
__device__ u64    g_remwD [2][NB][WRD];      // double-buffered kept suppression
__device__ float4 g_kbox  [NB][TOPN];
__device__ float  g_karea [NB][TOPN];
__device__ int    g_keptIdx[NB][TOPN];
__device__ int    g_keptCnt[NB];
__device__ int    g_kcMask[2][NB];           // kept count visible to maskers
__device__ int    g_dlo[NB], g_dhi[NB];      // delta range (prev window's keeps)
__device__ int    g_done  [NB];

// IoU>0.7 bits of box (bi,ai) vs 64 smem boxes starting at wb.
// Branch-free band + exact __fdiv_rn resolution (reference op order).
__device__ __forceinline__ u64 iou_word(float4 bi, float ai,
                                        const float4* cbx, const float* car,
                                        int wb)
{
    u64 bsup = 0, bamb = 0;
#pragma unroll 8
    for (int j2 = 0; j2 < 64; j2++) {
        float4 bj = cbx[wb + j2];
        float  aj = car[wb + j2];
        float iw = fmaxf(__fadd_rn(__fsub_rn(fminf(bi.z, bj.z), fmaxf(bi.x, bj.x)), 1.0f), 0.0f);
        float ih = fmaxf(__fadd_rn(__fsub_rn(fminf(bi.w, bj.w), fmaxf(bi.y, bj.y)), 1.0f), 0.0f);
        float inter = __fmul_rn(iw, ih);
        float s     = __fadd_rn(ai, aj);
        bool hi = inter > __fmul_rn(s, 0.411775f);
        bool lo = inter < __fmul_rn(s, 0.411755f);
        bsup |= ((u64)hi) << j2;
        bamb |= ((u64)(!hi && !lo)) << j2;
    }
    while (bamb) {
        int j2 = __ffsll((long long)bamb) - 1;
        bamb &= bamb - 1;
        float4 bj = cbx[wb + j2];
        float iw = fmaxf(__fadd_rn(__fsub_rn(fminf(bi.z, bj.z), fmaxf(bi.x, bj.x)), 1.0f), 0.0f);
        float ih = fmaxf(__fadd_rn(__fsub_rn(fminf(bi.w, bj.w), fmaxf(bi.y, bj.y)), 1.0f), 0.0f);
        float inter = __fmul_rn(iw, ih);
        float s     = __fadd_rn(ai, car[wb + j2]);
        float denom = __fsub_rn(s, inter);
        if (__fdiv_rn(inter, denom) > 0.7f) bsup |= (1ull << j2);
    }
    return bsup;
}

// ---------------------------------------------------------------- prep ----
__global__ __launch_bounds__(256) void k_prep(const float* __restrict__ sm,
                                              const float* __restrict__ bd,
                                              const float* __restrict__ img)
{
    int b = blockIdx.y;
    int i = blockIdx.x * 256 + threadIdx.x;       // 0..NPAD-1
    if (i == 0) {
        g_done[b] = 0; g_keptCnt[b] = 0;
        g_kcMask[0][b] = 0; g_kcMask[1][b] = 0;
        g_dlo[b] = 0; g_dhi[b] = 0;
    }
    if (i < 2 * WRD) g_remwD[i >> 4][b][i & 15] = 0;
    if (i >= NPAD) return;
    if (i >= NPROP) { g_keys[b * NPAD + i] = ~0ull; return; }

    int a  = i % NA;
    int hw = i / NA;
    float cx = (float)((hw & 63) * 16 + 8);
    float cy = (float)((hw >> 6) * 16 + 8);

    float ax1 = cx + c_anchors[a][0];
    float ay1 = cy + c_anchors[a][1];
    float ax2 = cx + c_anchors[a][2];
    float ay2 = cy + c_anchors[a][3];

    float wA = ax2 - ax1 + 1.0f;                  // exact small integers
    float hA = ay2 - ay1 + 1.0f;
    float ctrx = __fadd_rn(ax1, __fmul_rn(0.5f, wA));
    float ctry = __fadd_rn(ay1, __fmul_rn(0.5f, hA));

    const float* bdb = bd + ((size_t)b * 36 + (size_t)a * 4) * NHW + hw;
    float dx = bdb[0];
    float dy = bdb[NHW];
    float dw = bdb[2 * NHW];
    float dh = bdb[3 * NHW];

    // reference op order: mul then add, no contraction
    float pcx = __fadd_rn(__fmul_rn(dx, wA), ctrx);
    float pcy = __fadd_rn(__fmul_rn(dy, hA), ctry);
    float pw  = __fmul_rn(expf(dw), wA);
    float ph  = __fmul_rn(expf(dh), hA);

    float x1 = __fsub_rn(pcx, __fmul_rn(0.5f, pw));
    float y1 = __fsub_rn(pcy, __fmul_rn(0.5f, ph));
    float x2 = __fadd_rn(pcx, __fmul_rn(0.5f, pw));
    float y2 = __fadd_rn(pcy, __fmul_rn(0.5f, ph));

    float imh = img[b * 3 + 0];
    float imw = img[b * 3 + 1];
    float mx  = __fsub_rn(imw, 1.0f);
    float my  = __fsub_rn(imh, 1.0f);
    x1 = fminf(fmaxf(x1, 0.0f), mx);
    x2 = fminf(fmaxf(x2, 0.0f), mx);
    y1 = fminf(fmaxf(y1, 0.0f), my);
    y2 = fminf(fmaxf(y2, 0.0f), my);

    float s = sm[((size_t)b * 18 + 9 + a) * NHW + hw];

    g_boxes[b][i]  = make_float4(x1, y1, x2, y2);
    g_scores[b][i] = s;

    unsigned u = __float_as_uint(s);
    unsigned k = (u & 0x80000000u) ? ~u : (u | 0x80000000u);  // ascending
    unsigned kd = ~k;                                          // descending
    g_keys[b * NPAD + i] = ((u64)kd << 32) | (unsigned)i;
}

// ---------------------------------------------------------------- sort ----
// 8192-element chunks in 64KB dynamic smem (16 blocks; measured 15.9us).
// Canonical bitonic: ascending iff ((li & len) == 0).
__global__ __launch_bounds__(1024) void k_sort_local(int startLen)
{
    extern __shared__ u64 sk[];
    int base = blockIdx.x * 8192;                 // flat over NB*NPAD
    int tid  = threadIdx.x;

#pragma unroll
    for (int e = 0; e < 8; e++) sk[e * 1024 + tid] = g_keys[base + e * 1024 + tid];
    __syncthreads();

    if (startLen == 0) {
        for (int len = 2; len <= 8192; len <<= 1) {
            for (int d = len >> 1; d > 0; d >>= 1) {
#pragma unroll
                for (int e = 0; e < 4; e++) {
                    int idx = e * 1024 + tid;          // 0..4095 pair ids
                    int i = ((idx & ~(d - 1)) << 1) | (idx & (d - 1));
                    int j = i | d;
                    int li = (base + i) & (NPAD - 1);
                    bool asc = ((li & len) == 0);
                    u64 a = sk[i], c = sk[j];
                    if ((a > c) == asc) { sk[i] = c; sk[j] = a; }
                }
                __syncthreads();
            }
        }
    } else {
        bool asc = (((base & (NPAD - 1)) & startLen) == 0);
        for (int d = 4096; d > 0; d >>= 1) {
#pragma unroll
            for (int e = 0; e < 4; e++) {
                int idx = e * 1024 + tid;
                int i = ((idx & ~(d - 1)) << 1) | (idx & (d - 1));
                int j = i | d;
                u64 a = sk[i], c = sk[j];
                if ((a > c) == asc) { sk[i] = c; sk[j] = a; }
            }
            __syncthreads();
        }
    }

#pragma unroll
    for (int e = 0; e < 8; e++) g_keys[base + e * 1024 + tid] = sk[e * 1024 + tid];
}

__global__ __launch_bounds__(256) void k_sort_global(int len, int d)
{
    int i = blockIdx.x * 256 + threadIdx.x;       // flat element index
    if (i >= NB * NPAD) return;
    int li = i & (NPAD - 1);
    if (li & d) return;
    int j = i + d;                                 // same batch since (li&d)==0
    bool asc = ((li & len) == 0);
    u64 a = g_keys[i], c = g_keys[j];
    if ((a > c) == asc) { g_keys[i] = c; g_keys[j] = a; }
}

// -------------------------------------------------------------- gather ----
__global__ __launch_bounds__(256) void k_gather()
{
    int b = blockIdx.y;
    int p = blockIdx.x * 256 + threadIdx.x;
    if (p >= NPROP) return;
    unsigned idx = (unsigned)(g_keys[b * NPAD + p] & 0xFFFFFFFFull);
    float4 bx = g_boxes[b][idx];
    g_sbox[b][p]   = bx;
    g_sscore[b][p] = g_scores[b][idx];
    g_sarea[b][p]  = __fmul_rn(__fadd_rn(__fsub_rn(bx.z, bx.x), 1.0f),
                               __fadd_rn(__fsub_rn(bx.w, bx.y), 1.0f));
}

// ------------------------------------------------------------ prologue ----
// In-window mask of window 0 -> g_wmask[0]. Grid (16, NB).
__global__ __launch_bounds__(512) void k_mask0()
{
    int b  = blockIdx.y;
    int rb = blockIdx.x;
    int t  = threadIdx.x;
    int rl = t & 63;
    int cg = t >> 6;

    __shared__ float4 cbx[WIN];
    __shared__ float  car[WIN];
    for (int j = t; j < WIN; j += 512) {
        cbx[j] = g_sbox[b][j];
        car[j] = g_sarea[b][j];
    }
    __syncthreads();
    int i = rb * 64 + rl;
    float4 bi = g_sbox[b][i];
    float  ai = g_sarea[b][i];
#pragma unroll
    for (int ww = 0; ww < 2; ww++) {
        int w = cg * 2 + ww;
        u64 v = iou_word(bi, ai, cbx, car, w * 64);
        if (w == rb) v &= (rl == 63) ? 0ull : (~0ull << (rl + 1));
        g_wmask[0][b][w][rb * 64 + rl] = v;
    }
}

// ------------------------------------------------------------ step k ----
// Grid (49, NB). All producer->consumer edges cross launch boundaries.
//   block 48:  resolve window k: rem = g_remwD[k&1] | delta(keeps of window
//              k-1 vs window k), then greedy resolve from g_wmask[k&1] in
//              smem. Publishes keeps, g_kcMask[(k+1)&1], g_dlo/g_dhi, and
//              zeroes g_remwD[k&1] for reuse in launch k+2.
//   blocks 0-15:  in-window mask of window k+1 -> g_wmask[(k+1)&1].
//   blocks 16-47: kept[0..g_kcMask[k&1]) vs window k+1 -> g_remwD[(k+1)&1].
__global__ __launch_bounds__(512) void k_step(int k)
{
    int b = blockIdx.y;
    if (g_done[b]) return;
    int bx = blockIdx.x;
    int t  = threadIdx.x;
    int rl = t & 63;
    int cg = t >> 6;
    int kn = k + 1;
    int par = k & 1;

    extern __shared__ char dynsmem[];
    u64*    blk = (u64*)dynsmem;                       // 128KB (resolver)
    float4* cbx = (float4*)(dynsmem + 131072);         // 16KB
    float*  car = (float*)(dynsmem + 131072 + 16384);  // 4KB

    if (bx == 48) {
        // ---------------- resolver for window k ----------------
        __shared__ u64 rem[WRD];
        __shared__ short ckeptL[WIN];
        __shared__ int s_kept, s_nk, s_nkc, s_done;

        for (int j = t; j < WIN; j += 512) {
            cbx[j] = g_sbox[b][k * WIN + j];
            car[j] = g_sarea[b][k * WIN + j];
        }
        const ulonglong2* src = (const ulonglong2*)&g_wmask[par][b][0][0];
        ulonglong2* dst = (ulonglong2*)blk;
#pragma unroll
        for (int q = 0; q < WRD; q++) dst[q * 512 + t] = src[q * 512 + t];
        if (t < WRD) rem[t] = g_remwD[par][b][t];
        if (t == 0) { s_kept = g_keptCnt[b]; s_done = 0; s_nkc = 0; }
        __syncthreads();

        // delta: keeps of window k-1 vs window k (range published last launch)
        int dlo = g_dlo[b], dhi = g_dhi[b];
        for (int q = dlo + (t >> 4); q < dhi; q += 32) {
            float4 bi = g_kbox[b][q];
            float  ai = g_karea[b][q];
            u64 v = iou_word(bi, ai, cbx, car, (t & 15) * 64);
            if (v) atomicOr(&rem[t & 15], v);
        }
        __syncthreads();

        for (int wl = 0; wl < WRD; wl++) {
            if (t == 0) {
                u64 alive = ~rem[wl];
                int nk = 0, kept = s_kept, nkc = s_nkc;
                while (alive && kept < TOPN) {
                    int j = __ffsll((long long)alive) - 1;
                    int lr = wl * 64 + j;
                    g_keptIdx[b][kept++] = k * WIN + lr;
                    ckeptL[nkc++] = (short)lr;
                    nk++;
                    alive &= ~blk[wl * WIN + lr];
                    alive &= ~(1ull << j);
                }
                s_nk = nk; s_kept = kept; s_nkc = nkc;
                if (kept >= TOPN) s_done = 1;
            }
            __syncthreads();
            if (s_done) break;
            int nk = s_nk;
            if (nk > 0 && t < WRD - 1 - wl) {
                int w2 = wl + 1 + t;
                u64 acc = rem[w2];
                int q0 = s_nkc - nk;
                for (int q = q0; q < s_nkc; q++) acc |= blk[w2 * WIN + ckeptL[q]];
                rem[w2] = acc;
            }
            __syncthreads();
        }

        // publish keeps + handoff state
        __syncthreads();
        int nkc = s_nkc;
        int kept0 = s_kept - nkc;
        for (int q = t; q < nkc; q += 512) {
            int c = k * WIN + ckeptL[q];
            g_kbox[b][kept0 + q]  = g_sbox[b][c];
            g_karea[b][kept0 + q] = g_sarea[b][c];
        }
        if (t < WRD) g_remwD[par][b][t] = 0;       // reuse in launch k+2
        if (t == 0) {
            g_keptCnt[b] = s_kept;
            g_kcMask[par ^ 1][b] = s_kept;         // maskers of launch k+1
            g_dlo[b] = kept0; g_dhi[b] = s_kept;   // delta for launch k+1
            if (s_done) g_done[b] = 1;
        }
    } else if (bx < 16) {
        // ------------- in-window mask of window k+1 -------------
        if (kn >= NWIN) return;
        for (int j = t; j < WIN; j += 512) {
            cbx[j] = g_sbox[b][kn * WIN + j];
            car[j] = g_sarea[b][kn * WIN + j];
        }
        __syncthreads();
        int rb = bx;
        int i  = kn * WIN + rb * 64 + rl;
        float4 bi = g_sbox[b][i];
        float  ai = g_sarea[b][i];
#pragma unroll
        for (int ww = 0; ww < 2; ww++) {
            int w = cg * 2 + ww;
            u64 v = iou_word(bi, ai, cbx, car, w * 64);
            if (w == rb) v &= (rl == 63) ? 0ull : (~0ull << (rl + 1));
            g_wmask[par ^ 1][b][w][rb * 64 + rl] = v;
        }
    } else {
        // -------- kept(through k-1) vs window k+1 --------
        if (kn >= NWIN) return;
        int keptCnt = g_kcMask[par][b];            // stable: written last launch
        int kb = bx - 16;                          // 0..31
        if (kb * 64 >= keptCnt) return;
        __shared__ u64 red[WRD];
        if (t < WRD) red[t] = 0;
        for (int j = t; j < WIN; j += 512) {
            cbx[j] = g_sbox[b][kn * WIN + j];
            car[j] = g_sarea[b][kn * WIN + j];
        }
        __syncthreads();
        int kr = kb * 64 + rl;
        if (kr < keptCnt) {
            float4 bi = g_kbox[b][kr];
            float  ai = g_karea[b][kr];
#pragma unroll
            for (int ww = 0; ww < 2; ww++) {
                int w = cg * 2 + ww;
                u64 v = iou_word(bi, ai, cbx, car, w * 64);
                if (v) atomicOr(&red[w], v);
            }
        }
        __syncthreads();
        if (t < WRD && red[t]) atomicOr((u64*)&g_remwD[par ^ 1][b][t], red[t]);
    }
}

// ----------------------------------------------------------------- out ----
__global__ __launch_bounds__(256) void k_out(float* __restrict__ out)
{
    int idx = blockIdx.x * 256 + threadIdx.x;
    if (idx >= NB * TOPN) return;
    int b = idx / TOPN;
    int r = idx - b * TOPN;
    float* o = out + (size_t)idx * 5;
    if (r < g_keptCnt[b]) {
        int c = g_keptIdx[b][r];
        float4 bx = g_sbox[b][c];
        o[0] = g_sscore[b][c];
        o[1] = bx.x; o[2] = bx.y; o[3] = bx.z; o[4] = bx.w;
    } else {
        o[0] = 0.f; o[1] = 0.f; o[2] = 0.f; o[3] = 0.f; o[4] = 0.f;
    }
}

extern "C" void kernel_launch(void* const* d_in, const int* in_sizes, int n_in,
                              void* d_out, int out_size)
{
    const float* sm  = (const float*)d_in[0];
    const float* bd  = (const float*)d_in[1];
    const float* img = (const float*)d_in[2];
    float* out = (float*)d_out;

    cudaFuncSetAttribute(k_sort_local,
                         cudaFuncAttributeMaxDynamicSharedMemorySize, 65536);
    cudaFuncSetAttribute(k_step,
                         cudaFuncAttributeMaxDynamicSharedMemorySize, 151552);

    k_prep<<<dim3(NPAD / 256, NB), 256>>>(sm, bd, img);

    const int nchunks = NB * NPAD / 8192;          // 16
    k_sort_local<<<nchunks, 1024, 65536>>>(0);
    k_sort_global<<<NB * NPAD / 256, 256>>>(16384, 8192);
    k_sort_local<<<nchunks, 1024, 65536>>>(16384);
    k_sort_global<<<NB * NPAD / 256, 256>>>(32768, 16384);
    k_sort_global<<<NB * NPAD / 256, 256>>>(32768, 8192);
    k_sort_local<<<nchunks, 1024, 65536>>>(32768);
    k_sort_global<<<NB * NPAD / 256, 256>>>(65536, 32768);
    k_sort_global<<<NB * NPAD / 256, 256>>>(65536, 16384);
    k_sort_global<<<NB * NPAD / 256, 256>>>(65536, 8192);
    k_sort_local<<<nchunks, 1024, 65536>>>(65536);

    k_gather<<<dim3(NPROP / 256, NB), 256>>>();

    k_mask0<<<dim3(16, NB), 512>>>();
    for (int k = 0; k < NWIN; k++)
        k_step<<<dim3(49, NB), 512, 151552>>>(k);

    k_out<<<(NB * TOPN + 255) / 256, 256>>>(out);
}

// round 16
// speedup vs baseline: 3.2399x; 3.2399x over previous
#include <cuda_runtime.h>
#include <cstdint>

#define NB    2
#define NA    9
#define NHW   4096        // 64*64
#define NPROP 36864       // NHW*NA
#define NPAD  65536
#define TOPN  2000
#define WIN   1024        // candidates per window
#define WRD   16          // 64-bit words per window
#define NWIN  36          // WIN*NWIN = NPROP
#define HEADW 16          // windows with per-window launches
#define TW    (NWIN-HEADW) // 20 tail windows, compressed into 2 launches

typedef unsigned long long u64;

// Anchors from generate_anchors(16,(0.5,1,2),(8,16,32)) with base [0,0,15,15].
__constant__ float c_anchors[9][4] = {
  { -84.f,  -40.f,  99.f,  55.f},
  {-176.f,  -88.f, 191.f, 103.f},
  {-360.f, -184.f, 375.f, 199.f},
  { -56.f,  -56.f,  71.f,  71.f},
  {-120.f, -120.f, 135.f, 135.f},
  {-248.f, -248.f, 263.f, 263.f},
  { -36.f,  -80.f,  51.f,  95.f},
  { -80.f, -168.f,  95.f, 183.f},
  {-168.f, -344.f, 183.f, 359.f}
};

__device__ float4 g_boxes [NB][NPROP];
__device__ float  g_scores[NB][NPROP];
__device__ u64    g_keys  [NB * NPAD];
__device__ float4 g_sbox  [NB][NPROP];
__device__ float  g_sscore[NB][NPROP];
__device__ float  g_sarea [NB][NPROP];
__device__ u64    g_wmask [NB][WRD][WIN];      // head window mask, [word][row]
__device__ u64    g_remw  [NB][WRD];           // head kept-suppression
__device__ u64    g_tmask [NB][TW][WRD][WIN];  // tail window masks (5MB)
__device__ u64    g_remT  [NB][TW][WRD];       // head-keeps suppression per tail win
__device__ float4 g_kbox  [NB][TOPN];
__device__ float  g_karea [NB][TOPN];
__device__ int    g_keptIdx[NB][TOPN];
__device__ int    g_keptCnt[NB];
__device__ int    g_done  [NB];

// IoU>0.7 bits of box (bi,ai) vs 64 smem boxes starting at wb.
// Branch-free band + exact __fdiv_rn resolution (reference op order).
__device__ __forceinline__ u64 iou_word(float4 bi, float ai,
                                        const float4* cbx, const float* car,
                                        int wb)
{
    u64 bsup = 0, bamb = 0;
#pragma unroll 8
    for (int j2 = 0; j2 < 64; j2++) {
        float4 bj = cbx[wb + j2];
        float  aj = car[wb + j2];
        float iw = fmaxf(__fadd_rn(__fsub_rn(fminf(bi.z, bj.z), fmaxf(bi.x, bj.x)), 1.0f), 0.0f);
        float ih = fmaxf(__fadd_rn(__fsub_rn(fminf(bi.w, bj.w), fmaxf(bi.y, bj.y)), 1.0f), 0.0f);
        float inter = __fmul_rn(iw, ih);
        float s     = __fadd_rn(ai, aj);
        bool hi = inter > __fmul_rn(s, 0.411775f);
        bool lo = inter < __fmul_rn(s, 0.411755f);
        bsup |= ((u64)hi) << j2;
        bamb |= ((u64)(!hi && !lo)) << j2;
    }
    while (bamb) {
        int j2 = __ffsll((long long)bamb) - 1;
        bamb &= bamb - 1;
        float4 bj = cbx[wb + j2];
        float iw = fmaxf(__fadd_rn(__fsub_rn(fminf(bi.z, bj.z), fmaxf(bi.x, bj.x)), 1.0f), 0.0f);
        float ih = fmaxf(__fadd_rn(__fsub_rn(fminf(bi.w, bj.w), fmaxf(bi.y, bj.y)), 1.0f), 0.0f);
        float inter = __fmul_rn(iw, ih);
        float s     = __fadd_rn(ai, car[wb + j2]);
        float denom = __fsub_rn(s, inter);
        if (__fdiv_rn(inter, denom) > 0.7f) bsup |= (1ull << j2);
    }
    return bsup;
}

// ---------------------------------------------------------------- prep ----
__global__ __launch_bounds__(256) void k_prep(const float* __restrict__ sm,
                                              const float* __restrict__ bd,
                                              const float* __restrict__ img)
{
    int b = blockIdx.y;
    int i = blockIdx.x * 256 + threadIdx.x;       // 0..NPAD-1
    if (i == 0) { g_done[b] = 0; g_keptCnt[b] = 0; }
    if (i < WRD) g_remw[b][i] = 0;
    if (i < TW * WRD) g_remT[b][i >> 4][i & 15] = 0;
    if (i >= NPAD) return;
    if (i >= NPROP) { g_keys[b * NPAD + i] = ~0ull; return; }

    int a  = i % NA;
    int hw = i / NA;
    float cx = (float)((hw & 63) * 16 + 8);
    float cy = (float)((hw >> 6) * 16 + 8);

    float ax1 = cx + c_anchors[a][0];
    float ay1 = cy + c_anchors[a][1];
    float ax2 = cx + c_anchors[a][2];
    float ay2 = cy + c_anchors[a][3];

    float wA = ax2 - ax1 + 1.0f;                  // exact small integers
    float hA = ay2 - ay1 + 1.0f;
    float ctrx = __fadd_rn(ax1, __fmul_rn(0.5f, wA));
    float ctry = __fadd_rn(ay1, __fmul_rn(0.5f, hA));

    const float* bdb = bd + ((size_t)b * 36 + (size_t)a * 4) * NHW + hw;
    float dx = bdb[0];
    float dy = bdb[NHW];
    float dw = bdb[2 * NHW];
    float dh = bdb[3 * NHW];

    // reference op order: mul then add, no contraction
    float pcx = __fadd_rn(__fmul_rn(dx, wA), ctrx);
    float pcy = __fadd_rn(__fmul_rn(dy, hA), ctry);
    float pw  = __fmul_rn(expf(dw), wA);
    float ph  = __fmul_rn(expf(dh), hA);

    float x1 = __fsub_rn(pcx, __fmul_rn(0.5f, pw));
    float y1 = __fsub_rn(pcy, __fmul_rn(0.5f, ph));
    float x2 = __fadd_rn(pcx, __fmul_rn(0.5f, pw));
    float y2 = __fadd_rn(pcy, __fmul_rn(0.5f, ph));

    float imh = img[b * 3 + 0];
    float imw = img[b * 3 + 1];
    float mx  = __fsub_rn(imw, 1.0f);
    float my  = __fsub_rn(imh, 1.0f);
    x1 = fminf(fmaxf(x1, 0.0f), mx);
    x2 = fminf(fmaxf(x2, 0.0f), mx);
    y1 = fminf(fmaxf(y1, 0.0f), my);
    y2 = fminf(fmaxf(y2, 0.0f), my);

    float s = sm[((size_t)b * 18 + 9 + a) * NHW + hw];

    g_boxes[b][i]  = make_float4(x1, y1, x2, y2);
    g_scores[b][i] = s;

    unsigned u = __float_as_uint(s);
    unsigned k = (u & 0x80000000u) ? ~u : (u | 0x80000000u);  // ascending
    unsigned kd = ~k;                                          // descending
    g_keys[b * NPAD + i] = ((u64)kd << 32) | (unsigned)i;
}

// ---------------------------------------------------------------- sort ----
// 8192-element chunks in 64KB dynamic smem (16 blocks; measured 15.9us).
// Canonical bitonic: ascending iff ((li & len) == 0).
__global__ __launch_bounds__(1024) void k_sort_local(int startLen)
{
    extern __shared__ u64 sk[];
    int base = blockIdx.x * 8192;                 // flat over NB*NPAD
    int tid  = threadIdx.x;

#pragma unroll
    for (int e = 0; e < 8; e++) sk[e * 1024 + tid] = g_keys[base + e * 1024 + tid];
    __syncthreads();

    if (startLen == 0) {
        for (int len = 2; len <= 8192; len <<= 1) {
            for (int d = len >> 1; d > 0; d >>= 1) {
#pragma unroll
                for (int e = 0; e < 4; e++) {
                    int idx = e * 1024 + tid;          // 0..4095 pair ids
                    int i = ((idx & ~(d - 1)) << 1) | (idx & (d - 1));
                    int j = i | d;
                    int li = (base + i) & (NPAD - 1);
                    bool asc = ((li & len) == 0);
                    u64 a = sk[i], c = sk[j];
                    if ((a > c) == asc) { sk[i] = c; sk[j] = a; }
                }
                __syncthreads();
            }
        }
    } else {
        bool asc = (((base & (NPAD - 1)) & startLen) == 0);
        for (int d = 4096; d > 0; d >>= 1) {
#pragma unroll
            for (int e = 0; e < 4; e++) {
                int idx = e * 1024 + tid;
                int i = ((idx & ~(d - 1)) << 1) | (idx & (d - 1));
                int j = i | d;
                u64 a = sk[i], c = sk[j];
                if ((a > c) == asc) { sk[i] = c; sk[j] = a; }
            }
            __syncthreads();
        }
    }

#pragma unroll
    for (int e = 0; e < 8; e++) g_keys[base + e * 1024 + tid] = sk[e * 1024 + tid];
}

__global__ __launch_bounds__(256) void k_sort_global(int len, int d)
{
    int i = blockIdx.x * 256 + threadIdx.x;       // flat element index
    if (i >= NB * NPAD) return;
    int li = i & (NPAD - 1);
    if (li & d) return;
    int j = i + d;                                 // same batch since (li&d)==0
    bool asc = ((li & len) == 0);
    u64 a = g_keys[i], c = g_keys[j];
    if ((a > c) == asc) { g_keys[i] = c; g_keys[j] = a; }
}

// -------------------------------------------------------------- gather ----
__global__ __launch_bounds__(256) void k_gather()
{
    int b = blockIdx.y;
    int p = blockIdx.x * 256 + threadIdx.x;
    if (p >= NPROP) return;
    unsigned idx = (unsigned)(g_keys[b * NPAD + p] & 0xFFFFFFFFull);
    float4 bx = g_boxes[b][idx];
    g_sbox[b][p]   = bx;
    g_sscore[b][p] = g_scores[b][idx];
    g_sarea[b][p]  = __fmul_rn(__fadd_rn(__fsub_rn(bx.z, bx.x), 1.0f),
                               __fadd_rn(__fsub_rn(bx.w, bx.y), 1.0f));
}

// --------------------------------------------------- head window mask ----
// Phase k: blocks 0..15 compute the 1024x1024 in-window mask rows; blocks
// 16..47 OR previously-kept boxes vs the window's columns into g_remw.
__global__ __launch_bounds__(512) void k_maskw(int k)
{
    int b = blockIdx.y;
    if (g_done[b]) return;
    int bx = blockIdx.x;
    int keptCnt = g_keptCnt[b];
    if (bx >= 16 && (bx - 16) * 64 >= keptCnt) return;

    int t    = threadIdx.x;
    int rl   = t & 63;
    int cg   = t >> 6;
    int R0   = k * WIN;

    __shared__ float4 cbx[WIN];
    __shared__ float  car[WIN];
    for (int j = t; j < WIN; j += 512) {
        cbx[j] = g_sbox[b][R0 + j];
        car[j] = g_sarea[b][R0 + j];
    }
    __shared__ u64 red[WRD];
    if (t < WRD) red[t] = 0;
    __syncthreads();

    if (bx < 16) {
        int i = R0 + bx * 64 + rl;
        float4 bi = g_sbox[b][i];
        float  ai = g_sarea[b][i];
#pragma unroll
        for (int ww = 0; ww < 2; ww++) {
            int w = cg * 2 + ww;
            u64 v = iou_word(bi, ai, cbx, car, w * 64);
            if (w == bx) v &= (rl == 63) ? 0ull : (~0ull << (rl + 1));
            g_wmask[b][w][bx * 64 + rl] = v;
        }
    } else {
        int kr = (bx - 16) * 64 + rl;
        if (kr < keptCnt) {
            float4 bi = g_kbox[b][kr];
            float  ai = g_karea[b][kr];
#pragma unroll
            for (int ww = 0; ww < 2; ww++) {
                int w = cg * 2 + ww;
                u64 v = iou_word(bi, ai, cbx, car, w * 64);
                if (v) atomicOr(&red[w], v);
            }
        }
        __syncthreads();
        if (t < WRD && red[t]) atomicOr((u64*)&g_remw[b][t], red[t]);
    }
}

// --------------------------------------------------- head window scan ----
__global__ __launch_bounds__(512) void k_scanw(int k)
{
    int b = blockIdx.x;
    if (g_done[b]) return;
    int t = threadIdx.x;
    extern __shared__ u64 blk[];                  // [WRD][WIN]
    __shared__ u64 rem[WRD];
    __shared__ short ckeptL[WIN];
    __shared__ int s_kept, s_nk, s_nkc, s_done;

    const ulonglong2* src = (const ulonglong2*)&g_wmask[b][0][0];
    ulonglong2* dst = (ulonglong2*)blk;
#pragma unroll
    for (int q = 0; q < WRD; q++) dst[q * 512 + t] = src[q * 512 + t];
    if (t < WRD) rem[t] = g_remw[b][t];
    if (t == 0) { s_kept = g_keptCnt[b]; s_done = 0; s_nkc = 0; }
    __syncthreads();

    for (int wl = 0; wl < WRD; wl++) {
        if (t == 0) {
            u64 alive = ~rem[wl];
            int nk = 0, kept = s_kept, nkc = s_nkc;
            while (alive && kept < TOPN) {
                int j = __ffsll((long long)alive) - 1;
                int lr = wl * 64 + j;
                g_keptIdx[b][kept++] = k * WIN + lr;
                ckeptL[nkc++] = (short)lr;
                nk++;
                alive &= ~blk[wl * WIN + lr];
                alive &= ~(1ull << j);
            }
            s_nk = nk; s_kept = kept; s_nkc = nkc;
            if (kept >= TOPN) s_done = 1;
        }
        __syncthreads();
        if (s_done) break;
        int nk = s_nk;
        if (nk > 0 && t < WRD - 1 - wl) {
            int w2 = wl + 1 + t;
            u64 acc = rem[w2];
            int q0 = s_nkc - nk;
            for (int q = q0; q < s_nkc; q++) acc |= blk[w2 * WIN + ckeptL[q]];
            rem[w2] = acc;
        }
        __syncthreads();
    }

    __syncthreads();
    int nkc = s_nkc;
    int kept0 = s_kept - nkc;
    for (int q = t; q < nkc; q += 512) {
        int c = k * WIN + ckeptL[q];
        g_kbox[b][kept0 + q]  = g_sbox[b][c];
        g_karea[b][kept0 + q] = g_sarea[b][c];
    }
    if (t == 0) {
        g_keptCnt[b] = s_kept;
        if (s_done) g_done[b] = 1;
    }
    if (t < WRD) g_remw[b][t] = 0;
}

// ------------------------------------------------------------ tail mask ----
// One launch for ALL tail windows (done-gated). Grid (TW*16 + TW*32, NB):
//   bx < TW*16           : in-window mask of tail window wi=bx/16, rowgroup bx%16
//   bx >= TW*16          : head-keeps vs tail window wi, kept-block kb
__global__ __launch_bounds__(512) void k_masktail()
{
    int b = blockIdx.y;
    if (g_done[b]) return;
    int bx = blockIdx.x;
    int t  = threadIdx.x;
    int rl = t & 63;
    int cg = t >> 6;

    __shared__ float4 cbx[WIN];
    __shared__ float  car[WIN];
    __shared__ u64    red[WRD];

    if (bx < TW * 16) {
        int wi = bx >> 4;
        int rb = bx & 15;
        int R0 = (HEADW + wi) * WIN;
        for (int j = t; j < WIN; j += 512) {
            cbx[j] = g_sbox[b][R0 + j];
            car[j] = g_sarea[b][R0 + j];
        }
        __syncthreads();
        int i = R0 + rb * 64 + rl;
        float4 bi = g_sbox[b][i];
        float  ai = g_sarea[b][i];
#pragma unroll
        for (int ww = 0; ww < 2; ww++) {
            int w = cg * 2 + ww;
            u64 v = iou_word(bi, ai, cbx, car, w * 64);
            if (w == rb) v &= (rl == 63) ? 0ull : (~0ull << (rl + 1));
            g_tmask[b][wi][w][rb * 64 + rl] = v;
        }
    } else {
        int r2 = bx - TW * 16;
        int wi = r2 >> 5;                 // /32
        int kb = r2 & 31;
        int keptCnt = g_keptCnt[b];       // head keeps (stable: prior launch)
        if (kb * 64 >= keptCnt) return;
        int R0 = (HEADW + wi) * WIN;
        if (t < WRD) red[t] = 0;
        for (int j = t; j < WIN; j += 512) {
            cbx[j] = g_sbox[b][R0 + j];
            car[j] = g_sarea[b][R0 + j];
        }
        __syncthreads();
        int kr = kb * 64 + rl;
        if (kr < keptCnt) {
            float4 bi = g_kbox[b][kr];
            float  ai = g_karea[b][kr];
#pragma unroll
            for (int ww = 0; ww < 2; ww++) {
                int w = cg * 2 + ww;
                u64 v = iou_word(bi, ai, cbx, car, w * 64);
                if (v) atomicOr(&red[w], v);
            }
        }
        __syncthreads();
        if (t < WRD && red[t]) atomicOr((u64*)&g_remT[b][wi][t], red[t]);
    }
}

// ------------------------------------------------------------ tail scan ----
// One block per batch; loops all tail windows. Per window: load mask to smem,
// rem = g_remT[wi] | delta(tail keeps so far vs this window), resolve, append.
__global__ __launch_bounds__(512) void k_scantail()
{
    int b = blockIdx.x;
    if (g_done[b]) return;
    int t = threadIdx.x;

    extern __shared__ char dynsmem[];
    u64*    blk = (u64*)dynsmem;                       // 128KB
    float4* cbx = (float4*)(dynsmem + 131072);         // 16KB
    float*  car = (float*)(dynsmem + 131072 + 16384);  // 4KB

    __shared__ u64 rem[WRD];
    __shared__ short ckeptL[WIN];
    __shared__ int ckeptT[2048];                       // tail keeps (global idx)
    __shared__ int s_kept, s_nk, s_nkc, s_ntail, s_done;

    if (t == 0) { s_kept = g_keptCnt[b]; s_ntail = 0; s_done = 0; }
    __syncthreads();

    for (int wi = 0; wi < TW; wi++) {
        int k = HEADW + wi;
        for (int j = t; j < WIN; j += 512) {
            cbx[j] = g_sbox[b][k * WIN + j];
            car[j] = g_sarea[b][k * WIN + j];
        }
        const ulonglong2* src = (const ulonglong2*)&g_tmask[b][wi][0][0];
        ulonglong2* dst = (ulonglong2*)blk;
#pragma unroll
        for (int q = 0; q < WRD; q++) dst[q * 512 + t] = src[q * 512 + t];
        if (t < WRD) rem[t] = g_remT[b][wi][t];
        if (t == 0) { s_nkc = 0; }
        __syncthreads();

        // delta: tail keeps so far vs this window
        int ntail = s_ntail;
        for (int q = t >> 4; q < ntail; q += 32) {
            int c = ckeptT[q];
            float4 bi = g_sbox[b][c];
            float  ai = g_sarea[b][c];
            u64 v = iou_word(bi, ai, cbx, car, (t & 15) * 64);
            if (v) atomicOr(&rem[t & 15], v);
        }
        __syncthreads();

        for (int wl = 0; wl < WRD; wl++) {
            if (t == 0) {
                u64 alive = ~rem[wl];
                int nk = 0, kept = s_kept, nkc = s_nkc;
                while (alive && kept < TOPN) {
                    int j = __ffsll((long long)alive) - 1;
                    int lr = wl * 64 + j;
                    g_keptIdx[b][kept++] = k * WIN + lr;
                    ckeptL[nkc++] = (short)lr;
                    nk++;
                    alive &= ~blk[wl * WIN + lr];
                    alive &= ~(1ull << j);
                }
                s_nk = nk; s_kept = kept; s_nkc = nkc;
                if (kept >= TOPN) s_done = 1;
            }
            __syncthreads();
            if (s_done) break;
            int nk = s_nk;
            if (nk > 0 && t < WRD - 1 - wl) {
                int w2 = wl + 1 + t;
                u64 acc = rem[w2];
                int q0 = s_nkc - nk;
                for (int q = q0; q < s_nkc; q++) acc |= blk[w2 * WIN + ckeptL[q]];
                rem[w2] = acc;
            }
            __syncthreads();
        }

        // append this window's keeps (kbox for none-after, ckeptT for deltas)
        __syncthreads();
        int nkc = s_nkc;
        int kept0 = s_kept - nkc;
        for (int q = t; q < nkc; q += 512) {
            int c = k * WIN + ckeptL[q];
            g_kbox[b][kept0 + q]  = g_sbox[b][c];
            g_karea[b][kept0 + q] = g_sarea[b][c];
            ckeptT[s_ntail + q]   = c;
        }
        __syncthreads();
        if (t == 0) {
            s_ntail += nkc;
            g_keptCnt[b] = s_kept;
            if (s_done) g_done[b] = 1;
        }
        __syncthreads();
        if (s_done) break;
    }
}

// ----------------------------------------------------------------- out ----
__global__ __launch_bounds__(256) void k_out(float* __restrict__ out)
{
    int idx = blockIdx.x * 256 + threadIdx.x;
    if (idx >= NB * TOPN) return;
    int b = idx / TOPN;
    int r = idx - b * TOPN;
    float* o = out + (size_t)idx * 5;
    if (r < g_keptCnt[b]) {
        int c = g_keptIdx[b][r];
        float4 bx = g_sbox[b][c];
        o[0] = g_sscore[b][c];
        o[1] = bx.x; o[2] = bx.y; o[3] = bx.z; o[4] = bx.w;
    } else {
        o[0] = 0.f; o[1] = 0.f; o[2] = 0.f; o[3] = 0.f; o[4] = 0.f;
    }
}

extern "C" void kernel_launch(void* const* d_in, const int* in_sizes, int n_in,
                              void* d_out, int out_size)
{
    const float* sm  = (const float*)d_in[0];
    const float* bd  = (const float*)d_in[1];
    const float* img = (const float*)d_in[2];
    float* out = (float*)d_out;

    cudaFuncSetAttribute(k_sort_local,
                         cudaFuncAttributeMaxDynamicSharedMemorySize, 65536);
    cudaFuncSetAttribute(k_scanw,
                         cudaFuncAttributeMaxDynamicSharedMemorySize, 131072);
    cudaFuncSetAttribute(k_scantail,
                         cudaFuncAttributeMaxDynamicSharedMemorySize, 151552);

    k_prep<<<dim3(NPAD / 256, NB), 256>>>(sm, bd, img);

    const int nchunks = NB * NPAD / 8192;          // 16
    k_sort_local<<<nchunks, 1024, 65536>>>(0);
    k_sort_global<<<NB * NPAD / 256, 256>>>(16384, 8192);
    k_sort_local<<<nchunks, 1024, 65536>>>(16384);
    k_sort_global<<<NB * NPAD / 256, 256>>>(32768, 16384);
    k_sort_global<<<NB * NPAD / 256, 256>>>(32768, 8192);
    k_sort_local<<<nchunks, 1024, 65536>>>(32768);
    k_sort_global<<<NB * NPAD / 256, 256>>>(65536, 32768);
    k_sort_global<<<NB * NPAD / 256, 256>>>(65536, 16384);
    k_sort_global<<<NB * NPAD / 256, 256>>>(65536, 8192);
    k_sort_local<<<nchunks, 1024, 65536>>>(65536);

    k_gather<<<dim3(NPROP / 256, NB), 256>>>();

    for (int k = 0; k < HEADW; k++) {
        k_maskw<<<dim3(48, NB), 512>>>(k);
        k_scanw<<<NB, 512, 131072>>>(k);
    }
    k_masktail<<<dim3(TW * 48, NB), 512>>>();
    k_scantail<<<NB, 512, 151552>>>();

    k_out<<<(NB * TOPN + 255) / 256, 256>>>(out);
}